// round 6
// baseline (speedup 1.0000x reference)
#include <cuda_runtime.h>
#include <cuda_fp16.h>
#include <cstdint>

// Problem constants: P=8 segments, L=512 codes, D=64, N=1M tokens.
#define PP 8
#define LLEN 512
#define DD 64
#define CC (PP * LLEN)   // 4096 rows in transposed table

#define TILE_TOK 64                       // tokens per CTA tile (16 KB output)
#define WARPS 8                           // 256 threads
#define TOK_PER_WARP (TILE_TOK / WARPS)   // 8
#define PAIRS_PER_WARP (TOK_PER_WARP / 2) // 4

// Transposed + fp16-converted table: g_Wh[c][d] = (half)W[d][c]. 512 KB.
__device__ __half g_Wh[CC * DD];

__device__ __forceinline__ uint32_t smem_u32(const void* p) {
    uint32_t a;
    asm("{ .reg .u64 t; cvta.to.shared.u64 t, %1; cvt.u32.u64 %0, t; }"
        : "=r"(a) : "l"(p));
    return a;
}

// ---------------------------------------------------------------------------
// Transpose+convert W [D=64, C=4096] fp32 -> g_Wh [C=4096, D=64] fp16.
// One thread per table row c: coalesced reads, contiguous 128B row write.
// ---------------------------------------------------------------------------
__global__ void convert_w_kernel(const float* __restrict__ W) {
    int c = blockIdx.x * blockDim.x + threadIdx.x;   // 0 .. 4095
    if (c >= CC) return;

    __half hbuf[DD];
#pragma unroll
    for (int d = 0; d < DD; d++) {
        hbuf[d] = __float2half(W[d * CC + c]);
    }
    uint4* dst = reinterpret_cast<uint4*>(g_Wh + (size_t)c * DD);
    const uint4* src = reinterpret_cast<const uint4*>(hbuf);
#pragma unroll
    for (int k = 0; k < 8; k++) dst[k] = src[k];
}

// ---------------------------------------------------------------------------
// Per-pair gather + fp16 tree. Lane layout: t = lane>>4 (token of the pair),
// s = lane&15 (8B slot of the 128B row). Returns this lane's 16B of output.
// ---------------------------------------------------------------------------
__device__ __forceinline__ float4
gather_pair(const uint2* __restrict__ Wb, const int4* __restrict__ xv, int tok) {
    int4 i0 = xv[tok * 2 + 0];
    int4 i1 = xv[tok * 2 + 1];

    uint2 v0 = Wb[(size_t)(0 * LLEN + i0.x) * 16];
    uint2 v1 = Wb[(size_t)(1 * LLEN + i0.y) * 16];
    uint2 v2 = Wb[(size_t)(2 * LLEN + i0.z) * 16];
    uint2 v3 = Wb[(size_t)(3 * LLEN + i0.w) * 16];
    uint2 v4 = Wb[(size_t)(4 * LLEN + i1.x) * 16];
    uint2 v5 = Wb[(size_t)(5 * LLEN + i1.y) * 16];
    uint2 v6 = Wb[(size_t)(6 * LLEN + i1.z) * 16];
    uint2 v7 = Wb[(size_t)(7 * LLEN + i1.w) * 16];

    const __half2* h0 = reinterpret_cast<const __half2*>(&v0);
    const __half2* h1 = reinterpret_cast<const __half2*>(&v1);
    const __half2* h2 = reinterpret_cast<const __half2*>(&v2);
    const __half2* h3 = reinterpret_cast<const __half2*>(&v3);
    const __half2* h4 = reinterpret_cast<const __half2*>(&v4);
    const __half2* h5 = reinterpret_cast<const __half2*>(&v5);
    const __half2* h6 = reinterpret_cast<const __half2*>(&v6);
    const __half2* h7 = reinterpret_cast<const __half2*>(&v7);

    float res[4];
#pragma unroll
    for (int k = 0; k < 2; k++) {
        __half2 w01 = __hadd2(h0[k], h1[k]);
        __half2 w23 = __hadd2(h2[k], h3[k]);
        __half2 w45 = __hadd2(h4[k], h5[k]);
        __half2 w67 = __hadd2(h6[k], h7[k]);
        __half2 u0 = __hadd2(w01, w23);
        __half2 u1 = __hadd2(w45, w67);
        float2 f0 = __half22float2(u0);
        float2 f1 = __half22float2(u1);
        res[2 * k + 0] = f0.x + f1.x;
        res[2 * k + 1] = f0.y + f1.y;
    }
    return make_float4(res[0], res[1], res[2], res[3]);
}

// ---------------------------------------------------------------------------
// Gather-and-sum with TMA (async bulk) store epilogue.
// CTA tile = 64 tokens; results staged in smem (STS.128, ~4 cyc/warp vs
// STG.128 ~12 cyc/warp), then one 16 KB cp.async.bulk per tile moves them to
// GMEM on the async proxy, off the LSU critical path. Double-buffered.
// ---------------------------------------------------------------------------
__global__ void __launch_bounds__(256)
eif_gather_h_kernel(const int* __restrict__ x, float* __restrict__ out,
                    int n_tok, int n_tiles) {
    __shared__ __align__(16) float s_buf[2][TILE_TOK * DD];   // 2 x 16 KB

    int lane = threadIdx.x & 31;
    int wid  = threadIdx.x >> 5;
    int t    = lane >> 4;          // token of the pair
    int s    = lane & 15;          // 8B slot within the 128B table row

    const uint2* __restrict__ Wb = reinterpret_cast<const uint2*>(g_Wh) + s;
    const int4*  __restrict__ xv = reinterpret_cast<const int4*>(x);

    int j = 0;
    for (int tile = blockIdx.x; tile < n_tiles; tile += gridDim.x, j++) {
        int buf = j & 1;
        int tok_base = tile * TILE_TOK;

        if (tok_base + TILE_TOK <= n_tok) {
            // Make sure the bulk copy issued 2 iterations ago on this buffer
            // has finished READING the smem before we overwrite it.
            if (threadIdx.x == 0) {
                asm volatile("cp.async.bulk.wait_group.read 1;" ::: "memory");
            }
            __syncthreads();

#pragma unroll
            for (int pp = 0; pp < PAIRS_PER_WARP; pp++) {
                int tok_in_tile = wid * TOK_PER_WARP + pp * 2 + t;
                float4 r = gather_pair(Wb, xv, tok_base + tok_in_tile);
                // lane s writes floats [4s, 4s+4) of this token's smem row
                reinterpret_cast<float4*>(&s_buf[buf][tok_in_tile * DD])[s] = r;
            }
            __syncthreads();

            if (threadIdx.x == 0) {
                asm volatile("fence.proxy.async.shared::cta;" ::: "memory");
                uint32_t saddr = smem_u32(&s_buf[buf][0]);
                const float* gdst = out + (size_t)tok_base * DD;
                asm volatile(
                    "cp.async.bulk.global.shared::cta.bulk_group [%0], [%1], %2;"
                    :: "l"(gdst), "r"(saddr), "r"((int)(TILE_TOK * DD * 4))
                    : "memory");
                asm volatile("cp.async.bulk.commit_group;" ::: "memory");
            }
        } else {
            // Partial tail tile: direct STG path.
#pragma unroll
            for (int pp = 0; pp < PAIRS_PER_WARP; pp++) {
                int tok = tok_base + wid * TOK_PER_WARP + pp * 2 + t;
                if (tok < n_tok) {
                    float4 r = gather_pair(Wb, xv, tok);
                    __stcs(reinterpret_cast<float4*>(out + (size_t)tok * DD) + s, r);
                }
            }
        }
    }

    // All bulk stores issued by thread 0 must be complete (writes visible)
    // before the kernel can be considered done.
    if (threadIdx.x == 0) {
        asm volatile("cp.async.bulk.wait_group 0;" ::: "memory");
    }
}

// ---------------------------------------------------------------------------
// kernel_launch: d_in[0] = x (int32, N*8), d_in[1] = W (float32, 64*4096).
// ---------------------------------------------------------------------------
extern "C" void kernel_launch(void* const* d_in, const int* in_sizes, int n_in,
                              void* d_out, int out_size) {
    const int*   x = (const int*)d_in[0];
    const float* W = (const float*)d_in[1];
    float*       out = (float*)d_out;

    int n_tok = in_sizes[0] / PP;   // N

    // 1) Convert + transpose table to fp16.
    convert_w_kernel<<<(CC + 255) / 256, 256>>>(W);

    // 2) Gather-and-sum with async-bulk store epilogue.
    {
        int n_tiles = (n_tok + TILE_TOK - 1) / TILE_TOK;   // 16384 for N=1M
        int grid = n_tiles < 4096 ? n_tiles : 4096;
        eif_gather_h_kernel<<<grid, 256>>>(x, out, n_tok, n_tiles);
    }
}

// round 7
// speedup vs baseline: 1.1841x; 1.1841x over previous
#include <cuda_runtime.h>
#include <cuda_fp16.h>
#include <cstdint>

// Problem constants: P=8 segments, L=512 codes, D=64, N=1M tokens.
#define PP 8
#define LLEN 512
#define DD 64
#define CC (PP * LLEN)   // 4096 rows in transposed table

// Transposed + fp16-converted table: g_Wh[c][d] = (half)W[d][c]. 512 KB.
__device__ __half g_Wh[CC * DD];

// ---------------------------------------------------------------------------
// Transpose+convert W [D=64, C=4096] fp32 -> g_Wh [C=4096, D=64] fp16.
// One thread per table row c: coalesced reads, contiguous 128B row write.
// ---------------------------------------------------------------------------
__global__ void convert_w_kernel(const float* __restrict__ W) {
    int c = blockIdx.x * blockDim.x + threadIdx.x;   // 0 .. 4095
    if (c >= CC) return;

    __half hbuf[DD];
#pragma unroll
    for (int d = 0; d < DD; d++) {
        hbuf[d] = __float2half(W[d * CC + c]);
    }
    uint4* dst = reinterpret_cast<uint4*>(g_Wh + (size_t)c * DD);
    const uint4* src = reinterpret_cast<const uint4*>(hbuf);
#pragma unroll
    for (int k = 0; k < 8; k++) dst[k] = src[k];
}

// fp16 two-level tree + fp32 finish on 8 gathered uint2 (8B) slots.
__device__ __forceinline__ float4
reduce8(const uint2& v0, const uint2& v1, const uint2& v2, const uint2& v3,
        const uint2& v4, const uint2& v5, const uint2& v6, const uint2& v7) {
    const __half2* h0 = reinterpret_cast<const __half2*>(&v0);
    const __half2* h1 = reinterpret_cast<const __half2*>(&v1);
    const __half2* h2 = reinterpret_cast<const __half2*>(&v2);
    const __half2* h3 = reinterpret_cast<const __half2*>(&v3);
    const __half2* h4 = reinterpret_cast<const __half2*>(&v4);
    const __half2* h5 = reinterpret_cast<const __half2*>(&v5);
    const __half2* h6 = reinterpret_cast<const __half2*>(&v6);
    const __half2* h7 = reinterpret_cast<const __half2*>(&v7);
    float res[4];
#pragma unroll
    for (int k = 0; k < 2; k++) {
        __half2 w01 = __hadd2(h0[k], h1[k]);
        __half2 w23 = __hadd2(h2[k], h3[k]);
        __half2 w45 = __hadd2(h4[k], h5[k]);
        __half2 w67 = __hadd2(h6[k], h7[k]);
        __half2 u0 = __hadd2(w01, w23);
        __half2 u1 = __hadd2(w45, w67);
        float2 f0 = __half22float2(u0);
        float2 f1 = __half22float2(u1);
        res[2 * k + 0] = f0.x + f1.x;
        res[2 * k + 1] = f0.y + f1.y;
    }
    return make_float4(res[0], res[1], res[2], res[3]);
}

// ---------------------------------------------------------------------------
// Gather-and-sum: 4 tokens per warp as TWO interleaved pairs.
// Lane layout per pair: t = lane>>4 (token of the pair), s = lane&15
// (8B slot of the 128B table row). All 16 LDG.64 gathers are issued before
// any accumulation -> MLP=16 per warp, scoreboard exposure halved vs R5.
// ---------------------------------------------------------------------------
__global__ void __launch_bounds__(256)
eif_gather_h_kernel(const int* __restrict__ x, float* __restrict__ out, int n_tok) {
    int warp_id = (blockIdx.x * blockDim.x + threadIdx.x) >> 5;
    int lane    = threadIdx.x & 31;
    int t       = lane >> 4;
    int s       = lane & 15;

    int tokA = (warp_id << 2) + t;        // pair 0: tokens 4w+0, 4w+1
    int tokB = tokA + 2;                  // pair 1: tokens 4w+2, 4w+3
    if (tokB >= n_tok) {                  // tail: handle per-token
        if (tokA >= n_tok) return;
        const int4* xv = reinterpret_cast<const int4*>(x);
        int4 a0 = xv[tokA * 2 + 0], a1 = xv[tokA * 2 + 1];
        const uint2* __restrict__ Wb = reinterpret_cast<const uint2*>(g_Wh) + s;
        float4 r = reduce8(Wb[(size_t)(0 * LLEN + a0.x) * 16],
                           Wb[(size_t)(1 * LLEN + a0.y) * 16],
                           Wb[(size_t)(2 * LLEN + a0.z) * 16],
                           Wb[(size_t)(3 * LLEN + a0.w) * 16],
                           Wb[(size_t)(4 * LLEN + a1.x) * 16],
                           Wb[(size_t)(5 * LLEN + a1.y) * 16],
                           Wb[(size_t)(6 * LLEN + a1.z) * 16],
                           Wb[(size_t)(7 * LLEN + a1.w) * 16]);
        __stcs(reinterpret_cast<float4*>(out + (size_t)tokA * DD) + s, r);
        return;
    }

    // Hoisted index loads for both pairs (4 int4 per lane-token; the warp's
    // 4 tokens cover one contiguous 128B line of x).
    const int4* xv = reinterpret_cast<const int4*>(x);
    int4 a0 = xv[tokA * 2 + 0];
    int4 a1 = xv[tokA * 2 + 1];
    int4 b0 = xv[tokB * 2 + 0];
    int4 b1 = xv[tokB * 2 + 1];

    const uint2* __restrict__ Wb = reinterpret_cast<const uint2*>(g_Wh) + s;

    // Issue all 16 gathers (LDG.64, 2 lines each) before consuming any.
    uint2 pA0 = Wb[(size_t)(0 * LLEN + a0.x) * 16];
    uint2 pA1 = Wb[(size_t)(1 * LLEN + a0.y) * 16];
    uint2 pA2 = Wb[(size_t)(2 * LLEN + a0.z) * 16];
    uint2 pA3 = Wb[(size_t)(3 * LLEN + a0.w) * 16];
    uint2 pA4 = Wb[(size_t)(4 * LLEN + a1.x) * 16];
    uint2 pA5 = Wb[(size_t)(5 * LLEN + a1.y) * 16];
    uint2 pA6 = Wb[(size_t)(6 * LLEN + a1.z) * 16];
    uint2 pA7 = Wb[(size_t)(7 * LLEN + a1.w) * 16];

    uint2 pB0 = Wb[(size_t)(0 * LLEN + b0.x) * 16];
    uint2 pB1 = Wb[(size_t)(1 * LLEN + b0.y) * 16];
    uint2 pB2 = Wb[(size_t)(2 * LLEN + b0.z) * 16];
    uint2 pB3 = Wb[(size_t)(3 * LLEN + b0.w) * 16];
    uint2 pB4 = Wb[(size_t)(4 * LLEN + b1.x) * 16];
    uint2 pB5 = Wb[(size_t)(5 * LLEN + b1.y) * 16];
    uint2 pB6 = Wb[(size_t)(6 * LLEN + b1.z) * 16];
    uint2 pB7 = Wb[(size_t)(7 * LLEN + b1.w) * 16];

    // Pair A: accumulate + store while pair B's loads are still landing.
    float4 rA = reduce8(pA0, pA1, pA2, pA3, pA4, pA5, pA6, pA7);
    __stcs(reinterpret_cast<float4*>(out + (size_t)tokA * DD) + s, rA);

    // Pair B.
    float4 rB = reduce8(pB0, pB1, pB2, pB3, pB4, pB5, pB6, pB7);
    __stcs(reinterpret_cast<float4*>(out + (size_t)tokB * DD) + s, rB);
}

// ---------------------------------------------------------------------------
// kernel_launch: d_in[0] = x (int32, N*8), d_in[1] = W (float32, 64*4096).
// ---------------------------------------------------------------------------
extern "C" void kernel_launch(void* const* d_in, const int* in_sizes, int n_in,
                              void* d_out, int out_size) {
    const int*   x = (const int*)d_in[0];
    const float* W = (const float*)d_in[1];
    float*       out = (float*)d_out;

    int n_tok = in_sizes[0] / PP;   // N

    // 1) Convert + transpose table to fp16.
    convert_w_kernel<<<(CC + 255) / 256, 256>>>(W);

    // 2) Gather-and-sum: 4 tokens/warp, 8 warps/block -> 32 tokens/block.
    {
        int threads = 256;
        long long warps_needed = ((long long)n_tok + 3) / 4;
        long long blocks = (warps_needed + 7) / 8;
        eif_gather_h_kernel<<<(unsigned)blocks, threads>>>(x, out, n_tok);
    }
}